// round 13
// baseline (speedup 1.0000x reference)
#include <cuda_runtime.h>
#include <cuda_bf16.h>
#include <cstdint>

#define NROWS 8192
#define DIM   128
#define MARGIN 0.2f

#define BM 128
#define BN 128
#define KB 128              // bf16 K per row
#define NT 64               // 8192/128 tiles per dim
#define NTILES (NT * NT)    // 4096
#define GRIDP 304           // persistent CTAs (152 SMs x 2)

#define NSTAGE 3
#define STB  32768          // stage bytes: A 16KB + B 16KB (64 cols x 128 rows x 2B)
#define BOFF 16384          // B offset within a stage

#define WSUM_OFF (NSTAGE * STB)          // 98304
#define SMEM_TOTAL (WSUM_OFF + 64)

// device scratch
__device__ float  g_a[NROWS];            // yy[i]-2<x_i,y_i>+margin
__device__ float  g_b[NROWS];            // yy[j]
__device__ double g_cta[GRIDP];
__device__ __align__(16) __nv_bfloat16 g_xs[NROWS * KB];
__device__ __align__(16) __nv_bfloat16 g_ys[NROWS * KB];

__device__ __forceinline__ uint32_t smem_u32(const void* p) {
    uint32_t a;
    asm("{ .reg .u64 t; cvta.to.shared.u64 t, %1; cvt.u32.u64 %0, t; }" : "=r"(a) : "l"(p));
    return a;
}
__device__ __forceinline__ void cp16(uint32_t dst, const void* src) {
    asm volatile("cp.async.cg.shared.global [%0], [%1], 16;" :: "r"(dst), "l"(src));
}
#define CP_COMMIT() asm volatile("cp.async.commit_group;" ::: "memory")
#define CP_WAIT(n)  asm volatile("cp.async.wait_group %0;" :: "n"(n) : "memory")

#define LDSM4(r, addr) \
    asm volatile("ldmatrix.sync.aligned.m8n8.x4.shared.b16 {%0,%1,%2,%3}, [%4];" \
        : "=r"((r)[0]), "=r"((r)[1]), "=r"((r)[2]), "=r"((r)[3]) : "r"(addr))

// NOTE: non-volatile — register-pure, lets the scheduler interleave with loads
__device__ __forceinline__ void mma16816(float* c, const uint32_t* a,
                                         uint32_t b0, uint32_t b1) {
    asm("mma.sync.aligned.m16n8k16.row.col.f32.bf16.bf16.f32 "
        "{%0,%1,%2,%3}, {%4,%5,%6,%7}, {%8,%9}, {%0,%1,%2,%3};"
        : "+f"(c[0]), "+f"(c[1]), "+f"(c[2]), "+f"(c[3])
        : "r"(a[0]), "r"(a[1]), "r"(a[2]), "r"(a[3]), "r"(b0), "r"(b1));
}

// ---------------------------------------------------------------------------
// Precompute a[i], b[i] and bf16 rows. One warp per row.
// ---------------------------------------------------------------------------
__global__ void precompute_kernel(const float* __restrict__ x,
                                  const float* __restrict__ y) {
    int row  = blockIdx.x * 8 + (threadIdx.x >> 5);
    int lane = threadIdx.x & 31;

    float4 xv = reinterpret_cast<const float4*>(x + (size_t)row * DIM)[lane];
    float4 yv = reinterpret_cast<const float4*>(y + (size_t)row * DIM)[lane];

    float yy  = yv.x * yv.x + yv.y * yv.y + yv.z * yv.z + yv.w * yv.w;
    float dxy = xv.x * yv.x + xv.y * yv.y + xv.z * yv.z + xv.w * yv.w;

    __nv_bfloat162* xr = reinterpret_cast<__nv_bfloat162*>(g_xs + (size_t)row * KB);
    __nv_bfloat162* yr = reinterpret_cast<__nv_bfloat162*>(g_ys + (size_t)row * KB);
    xr[lane * 2 + 0] = __floats2bfloat162_rn(xv.x, xv.y);
    xr[lane * 2 + 1] = __floats2bfloat162_rn(xv.z, xv.w);
    yr[lane * 2 + 0] = __floats2bfloat162_rn(yv.x, yv.y);
    yr[lane * 2 + 1] = __floats2bfloat162_rn(yv.z, yv.w);

    #pragma unroll
    for (int off = 16; off > 0; off >>= 1) {
        yy  += __shfl_xor_sync(0xFFFFFFFFu, yy,  off);
        dxy += __shfl_xor_sync(0xFFFFFFFFu, dxy, off);
    }
    if (lane == 0) {
        g_b[row] = yy;
        g_a[row] = yy - 2.0f * dxy + MARGIN;
    }
}

// ---------------------------------------------------------------------------
// Persistent tile kernel. 304 CTAs x 256 threads, 2 CTAs/SM.
// Continuous 3-stage cp.async ring over 64-col K-chunks; fragment-level
// double buffering inside each chunk (LDSM s+1 issued under MMAs of s).
// ---------------------------------------------------------------------------
__device__ __forceinline__ void load_chunk(uint32_t sb, int bid, int cj, int tid) {
    int t   = bid + (cj >> 1) * GRIDP;
    int gm0 = (t >> 6) * BM;
    int gn0 = (t & 63) * BN;
    int k0  = (cj & 1) * 64;
    uint32_t base = sb + (uint32_t)(cj % 3) * STB;
    #pragma unroll
    for (int i = 0; i < 4; i++) {
        int f = i * 256 + tid;
        int r = f >> 3, cc = f & 7;
        uint32_t off = (uint32_t)(r * 128 + ((cc ^ (r & 7)) << 4));
        cp16(base + off,        g_xs + (size_t)(gm0 + r) * KB + k0 + cc * 8);
        cp16(base + BOFF + off, g_ys + (size_t)(gn0 + r) * KB + k0 + cc * 8);
    }
}

__device__ __forceinline__ void ldsm_step(uint32_t base, int s,
                                          int a_row, int a_kcl, int b_row, int b_kcl,
                                          uint32_t (&af)[4][4], uint32_t (&bf)[2][4]) {
    #pragma unroll
    for (int mi = 0; mi < 4; mi++) {
        int m  = a_row + mi * 16;
        int kc = 2 * s + a_kcl;
        LDSM4(af[mi], base + (uint32_t)(m * 128 + ((kc ^ (m & 7)) << 4)));
    }
    #pragma unroll
    for (int nb = 0; nb < 2; nb++) {
        int n  = b_row + nb * 16;
        int kc = 2 * s + b_kcl;
        LDSM4(bf[nb], base + BOFF + (uint32_t)(n * 128 + ((kc ^ (n & 7)) << 4)));
    }
}

__device__ __forceinline__ void mma_step(const uint32_t (&af)[4][4],
                                         const uint32_t (&bf)[2][4],
                                         float (&acc)[4][4][4]) {
    #pragma unroll
    for (int mi = 0; mi < 4; mi++) {
        #pragma unroll
        for (int nb = 0; nb < 2; nb++) {
            mma16816(acc[mi][2 * nb + 0], af[mi], bf[nb][0], bf[nb][1]);
            mma16816(acc[mi][2 * nb + 1], af[mi], bf[nb][2], bf[nb][3]);
        }
    }
}

__global__ void __launch_bounds__(256, 2)
tile_kernel() {
    extern __shared__ char smem[];
    const uint32_t sb = smem_u32(smem);
    const int bid  = blockIdx.x;
    const int tid  = threadIdx.x;
    const int wid  = tid >> 5;
    const int lane = tid & 31;
    const int wm   = wid >> 2;         // 0..1
    const int wn   = wid & 3;          // 0..3

    const int a_row = wm * 64 + ((lane >> 3) & 1) * 8 + (lane & 7);
    const int a_kcl = lane >> 4;
    const int b_row = wn * 32 + ((lane >> 4) & 1) * 8 + (lane & 7);
    const int b_kcl = (lane >> 3) & 1;
    const int g  = lane >> 2;
    const int tg = lane & 3;

    const int nt  = (NTILES - 1 - bid) / GRIDP + 1;   // tiles for this CTA
    const int nch = 2 * nt;

    // prologue: fill 2 of 3 stages
    load_chunk(sb, bid, 0, tid); CP_COMMIT();
    load_chunk(sb, bid, 1, tid); CP_COMMIT();

    float acc[4][4][4];
    #pragma unroll
    for (int i = 0; i < 4; i++)
        #pragma unroll
        for (int jj = 0; jj < 4; jj++)
            #pragma unroll
            for (int q = 0; q < 4; q++) acc[i][jj][q] = 0.0f;

    double s_run = 0.0;

    for (int j = 0; j < nch; j++) {
        CP_WAIT(1);                 // chunk j complete (j+1 may be pending)
        __syncthreads();            // all warps done with stage (j+2)%3's old data
        if (j + 2 < nch) load_chunk(sb, bid, j + 2, tid);
        CP_COMMIT();                // uniform group accounting (may be empty)

        const uint32_t base = sb + (uint32_t)(j % 3) * STB;

        // fragment-level double-buffered chunk: LDSM(s+1) issued before MMA(s)
        uint32_t af[2][4][4], bf[2][2][4];
        ldsm_step(base, 0, a_row, a_kcl, b_row, b_kcl, af[0], bf[0]);
        #pragma unroll
        for (int s = 0; s < 4; s++) {
            const int cur = s & 1;
            if (s < 3)
                ldsm_step(base, s + 1, a_row, a_kcl, b_row, b_kcl,
                          af[cur ^ 1], bf[cur ^ 1]);
            mma_step(af[cur], bf[cur], acc);
        }

        if (j & 1) {
            // tile (j>>1) finished: fused epilogue on register fragments
            int t   = bid + (j >> 1) * GRIDP;
            int gm0 = (t >> 6) * BM;
            int gn0 = (t & 63) * BN;
            float s = 0.0f;
            #pragma unroll
            for (int mi = 0; mi < 4; mi++) {
                int gi0 = gm0 + wm * 64 + mi * 16 + g;
                int gi1 = gi0 + 8;
                float a0 = __ldg(&g_a[gi0]);
                float a1 = __ldg(&g_a[gi1]);
                #pragma unroll
                for (int ni = 0; ni < 4; ni++) {
                    int gj0 = gn0 + wn * 32 + ni * 8 + tg * 2;
                    int gj1 = gj0 + 1;
                    float2 bb = __ldg(reinterpret_cast<const float2*>(&g_b[gj0]));
                    float v;
                    v = fmaf(2.0f, acc[mi][ni][0], a0 - bb.x); if (gi0 != gj0 && v > 0.0f) s += v;
                    v = fmaf(2.0f, acc[mi][ni][1], a0 - bb.y); if (gi0 != gj1 && v > 0.0f) s += v;
                    v = fmaf(2.0f, acc[mi][ni][2], a1 - bb.x); if (gi1 != gj0 && v > 0.0f) s += v;
                    v = fmaf(2.0f, acc[mi][ni][3], a1 - bb.y); if (gi1 != gj1 && v > 0.0f) s += v;
                    acc[mi][ni][0] = 0.0f; acc[mi][ni][1] = 0.0f;
                    acc[mi][ni][2] = 0.0f; acc[mi][ni][3] = 0.0f;
                }
            }
            s_run += (double)s;
        }
    }

    // ---- per-CTA deterministic reduction (once) ----
    #pragma unroll
    for (int off = 16; off > 0; off >>= 1)
        s_run += __shfl_xor_sync(0xFFFFFFFFu, s_run, off);
    double* wsum = reinterpret_cast<double*>(smem + WSUM_OFF);
    if (lane == 0) wsum[wid] = s_run;
    __syncthreads();
    if (tid == 0) {
        double tsum = 0.0;
        #pragma unroll
        for (int w = 0; w < 8; w++) tsum += wsum[w];
        g_cta[bid] = tsum;
    }
}

// ---------------------------------------------------------------------------
// Final reduction: 304 doubles -> mean. Deterministic.
// ---------------------------------------------------------------------------
__global__ void reduce_kernel(float* __restrict__ out) {
    __shared__ double sh[8];
    int tid = threadIdx.x;   // 256 threads

    double s = 0.0;
    for (int t = tid; t < GRIDP; t += 256) s += g_cta[t];

    #pragma unroll
    for (int off = 16; off > 0; off >>= 1)
        s += __shfl_xor_sync(0xFFFFFFFFu, s, off);
    if ((tid & 31) == 0) sh[tid >> 5] = s;
    __syncthreads();
    if (tid == 0) {
        double t = 0.0;
        #pragma unroll
        for (int w = 0; w < 8; w++) t += sh[w];
        out[0] = (float)(t / ((double)NROWS * (double)NROWS));
    }
}

// ---------------------------------------------------------------------------
extern "C" void kernel_launch(void* const* d_in, const int* in_sizes, int n_in,
                              void* d_out, int out_size) {
    const float* x = (const float*)d_in[0];
    const float* y = (const float*)d_in[1];
    float* out = (float*)d_out;

    cudaFuncSetAttribute(tile_kernel,
                         cudaFuncAttributeMaxDynamicSharedMemorySize, SMEM_TOTAL);

    precompute_kernel<<<NROWS / 8, 256>>>(x, y);
    tile_kernel<<<GRIDP, 256, SMEM_TOTAL>>>();
    reduce_kernel<<<1, 256>>>(out);
}

// round 14
// speedup vs baseline: 1.1068x; 1.1068x over previous
#include <cuda_runtime.h>
#include <cuda_bf16.h>
#include <cstdint>

#define NROWS 8192
#define DIM   128
#define MARGIN 0.2f

// ---- fallback (mma.sync) tiling ----
#define BM 128
#define BN 128
#define KB 128
#define NT 64
#define NTILES (NT * NT)
#define GRIDP 304
#define NSTAGE 3
#define STB  32768
#define BOFF 16384
#define WSUM_OFF (NSTAGE * STB)
#define SMEM_FB (WSUM_OFF + 64)

// ---- tcgen05 tiling ----
#define TCM 128
#define TCN 256
#define TC_NTM 64           // 8192/128
#define TC_NTN 32           // 8192/256
#define TC_BSH  16          // 256 floats b_sh: [16, 1040)
#define TC_WS   1040        // 8 floats wsum
#define TC_A_OFF 2048
#define TC_ASUB  16384      // one 64-col k-group of A (128 rows x 128B)
#define TC_B_OFF (TC_A_OFF + 2 * TC_ASUB)     // 34816 (1024-aligned)
#define TC_BSUB  32768      // one 64-col k-group of B (256 rows x 128B)
#define SMEM_TC (TC_B_OFF + 2 * TC_BSUB)      // 100352

// idesc: fp32 accum, bf16 x bf16, M=128, N=256 (formula validated vs 0x8080490)
#define IDESC_TC ((1u<<4) | (1u<<7) | (1u<<10) | ((TCN/8u)<<17) | ((TCM/16u)<<24))

// SW128 K-major descriptor base (Blackwell, LBO=1, SBO=64)
static constexpr uint64_t DESC_BASE =
    (uint64_t(2) << 61) | (uint64_t(1) << 46) | (uint64_t(64) << 32) | (uint64_t(1) << 16);

// ---- device scratch ----
__device__ float  g_a[NROWS];
__device__ float  g_b[NROWS];
__device__ double g_cta[GRIDP];              // fallback partials
__device__ float  g_tc[TC_NTM * TC_NTN];     // tcgen05 partials (zero if unused)
__device__ __align__(16) __nv_bfloat16 g_xs[NROWS * KB];
__device__ __align__(16) __nv_bfloat16 g_ys[NROWS * KB];

// ---------------- common helpers ----------------
__device__ __forceinline__ uint32_t smem_u32(const void* p) {
    uint32_t a;
    asm("{ .reg .u64 t; cvta.to.shared.u64 t, %1; cvt.u32.u64 %0, t; }" : "=r"(a) : "l"(p));
    return a;
}
__device__ __forceinline__ void cp16(uint32_t dst, const void* src) {
    asm volatile("cp.async.cg.shared.global [%0], [%1], 16;" :: "r"(dst), "l"(src));
}
#define CP_COMMIT() asm volatile("cp.async.commit_group;" ::: "memory")
#define CP_WAIT(n)  asm volatile("cp.async.wait_group %0;" :: "n"(n) : "memory")

#define LDSM4(r, addr) \
    asm volatile("ldmatrix.sync.aligned.m8n8.x4.shared.b16 {%0,%1,%2,%3}, [%4];" \
        : "=r"((r)[0]), "=r"((r)[1]), "=r"((r)[2]), "=r"((r)[3]) : "r"(addr))

__device__ __forceinline__ void mma16816(float* c, const uint32_t* a,
                                         uint32_t b0, uint32_t b1) {
    asm volatile(
        "mma.sync.aligned.m16n8k16.row.col.f32.bf16.bf16.f32 "
        "{%0,%1,%2,%3}, {%4,%5,%6,%7}, {%8,%9}, {%0,%1,%2,%3};"
        : "+f"(c[0]), "+f"(c[1]), "+f"(c[2]), "+f"(c[3])
        : "r"(a[0]), "r"(a[1]), "r"(a[2]), "r"(a[3]), "r"(b0), "r"(b1));
}

__device__ __forceinline__ uint32_t elect_one() {
    uint32_t p;
    asm volatile("{ .reg .pred p; elect.sync _|p, 0xFFFFFFFF; selp.b32 %0, 1, 0, p; }" : "=r"(p));
    return p;
}
#define MBAR_INIT(mb, c)  asm volatile("mbarrier.init.shared.b64 [%0], %1;" :: "r"(mb), "r"(c) : "memory")
#define FENCE_ASYNC()     asm volatile("fence.proxy.async.shared::cta;" ::: "memory")
__device__ __forceinline__ void mbar_wait(uint32_t mb, uint32_t parity) {
    asm volatile(
        "{\n\t.reg .pred P;\n\t"
        "W_%=: mbarrier.try_wait.parity.acquire.cta.shared::cta.b64 P, [%0], %1, 0x989680;\n\t"
        "@P bra.uni D_%=;\n\t bra.uni W_%=;\n\tD_%=:\n\t}"
        :: "r"(mb), "r"(parity) : "memory");
}

// ---------------- tcgen05 macros (expand only inside feature-guarded code) ----------------
#define TC_ALLOC(sm, n)   asm volatile("tcgen05.alloc.cta_group::1.sync.aligned.shared::cta.b32 [%0], %1;" :: "r"(sm), "r"(n) : "memory")
#define TC_DEALLOC(t, n)  asm volatile("tcgen05.dealloc.cta_group::1.sync.aligned.b32 %0, %1;" :: "r"(t), "r"(n))
#define TC_RELINQ()       asm volatile("tcgen05.relinquish_alloc_permit.cta_group::1.sync.aligned;")
#define TC_COMMIT(mb)     asm volatile("tcgen05.commit.cta_group::1.mbarrier::arrive::one.shared::cluster.b64 [%0];" :: "r"(mb) : "memory")
#define TC_WAIT_LD()      asm volatile("tcgen05.wait::ld.sync.aligned;" ::: "memory")
#define TC_FENCE_AFTER()  asm volatile("tcgen05.fence::after_thread_sync;" ::: "memory")
#define TC_FENCE_BEFORE() asm volatile("tcgen05.fence::before_thread_sync;" ::: "memory")
#define MMA_F16_SS(d, ad, bd, idesc, acc) \
    asm volatile( \
        "{\n\t.reg .pred p;\n\tsetp.ne.u32 p, %5, 0;\n\t" \
        "tcgen05.mma.cta_group::1.kind::f16 [%0], %1, %2, %3, {%4,%4,%4,%4}, p;\n\t}" \
        :: "r"(d), "l"(ad), "l"(bd), "r"(idesc), "r"(0u), "r"(acc) : "memory")
#define LDTM_X32(r, addr) \
    asm volatile("tcgen05.ld.sync.aligned.32x32b.x32.b32 " \
        "{%0,%1,%2,%3,%4,%5,%6,%7,%8,%9,%10,%11,%12,%13,%14,%15," \
        "%16,%17,%18,%19,%20,%21,%22,%23,%24,%25,%26,%27,%28,%29,%30,%31}, [%32];" \
        : "=r"((r)[0]),"=r"((r)[1]),"=r"((r)[2]),"=r"((r)[3]),"=r"((r)[4]),"=r"((r)[5]),"=r"((r)[6]),"=r"((r)[7]), \
          "=r"((r)[8]),"=r"((r)[9]),"=r"((r)[10]),"=r"((r)[11]),"=r"((r)[12]),"=r"((r)[13]),"=r"((r)[14]),"=r"((r)[15]), \
          "=r"((r)[16]),"=r"((r)[17]),"=r"((r)[18]),"=r"((r)[19]),"=r"((r)[20]),"=r"((r)[21]),"=r"((r)[22]),"=r"((r)[23]), \
          "=r"((r)[24]),"=r"((r)[25]),"=r"((r)[26]),"=r"((r)[27]),"=r"((r)[28]),"=r"((r)[29]),"=r"((r)[30]),"=r"((r)[31]) \
        : "r"(addr))

// ---------------------------------------------------------------------------
// Precompute a[i], b[i] and bf16 rows. One warp per row.
// ---------------------------------------------------------------------------
__global__ void precompute_kernel(const float* __restrict__ x,
                                  const float* __restrict__ y) {
    int row  = blockIdx.x * 8 + (threadIdx.x >> 5);
    int lane = threadIdx.x & 31;

    float4 xv = reinterpret_cast<const float4*>(x + (size_t)row * DIM)[lane];
    float4 yv = reinterpret_cast<const float4*>(y + (size_t)row * DIM)[lane];

    float yy  = yv.x * yv.x + yv.y * yv.y + yv.z * yv.z + yv.w * yv.w;
    float dxy = xv.x * yv.x + xv.y * yv.y + xv.z * yv.z + xv.w * yv.w;

    __nv_bfloat162* xr = reinterpret_cast<__nv_bfloat162*>(g_xs + (size_t)row * KB);
    __nv_bfloat162* yr = reinterpret_cast<__nv_bfloat162*>(g_ys + (size_t)row * KB);
    xr[lane * 2 + 0] = __floats2bfloat162_rn(xv.x, xv.y);
    xr[lane * 2 + 1] = __floats2bfloat162_rn(xv.z, xv.w);
    yr[lane * 2 + 0] = __floats2bfloat162_rn(yv.x, yv.y);
    yr[lane * 2 + 1] = __floats2bfloat162_rn(yv.z, yv.w);

    #pragma unroll
    for (int off = 16; off > 0; off >>= 1) {
        yy  += __shfl_xor_sync(0xFFFFFFFFu, yy,  off);
        dxy += __shfl_xor_sync(0xFFFFFFFFu, dxy, off);
    }
    if (lane == 0) {
        g_b[row] = yy;
        g_a[row] = yy - 2.0f * dxy + MARGIN;
    }
}

// ---------------------------------------------------------------------------
// tcgen05 tile kernel (body exists only in an sm_103a feature pass).
// One 128x256 tile per CTA; K=128 SS-mode, 8 dispatches; LDTM epilogue.
// ---------------------------------------------------------------------------
__global__ void __launch_bounds__(256, 2) __cluster_dims__(1, 1, 1)
tile_kernel_tc() {
#if !defined(__CUDA_ARCH__) || defined(__CUDA_ARCH_FEAT_SM103_ALL)
#if defined(__CUDA_ARCH__)
    extern __shared__ char smem[];
    const uint32_t sb = smem_u32(smem);
    const int tid  = threadIdx.x;
    const int wid  = tid >> 5;
    const int lane = tid & 31;
    const int gm0  = blockIdx.y * TCM;
    const int gn0  = blockIdx.x * TCN;

    // ---- cp.async loads: A 32KB, B 64KB, SW128 within 128B rows ----
    #pragma unroll
    for (int i = 0; i < 8; i++) {
        int f = i * 256 + tid;
        int r = f >> 4, rem = f & 15;
        int kg = rem >> 3, cc = rem & 7;
        uint32_t off = (uint32_t)(r * 128 + ((cc ^ (r & 7)) << 4));
        cp16(sb + TC_A_OFF + kg * TC_ASUB + off,
             g_xs + (size_t)(gm0 + r) * KB + kg * 64 + cc * 8);
    }
    #pragma unroll
    for (int i = 0; i < 16; i++) {
        int f = i * 256 + tid;
        int r = f >> 4, rem = f & 15;
        int kg = rem >> 3, cc = rem & 7;
        uint32_t off = (uint32_t)(r * 128 + ((cc ^ (r & 7)) << 4));
        cp16(sb + TC_B_OFF + kg * TC_BSUB + off,
             g_ys + (size_t)(gn0 + r) * KB + kg * 64 + cc * 8);
    }
    CP_COMMIT();

    if (wid == 0) {
        TC_ALLOC(sb + 0, 256);
        if (lane == 0) MBAR_INIT(sb + 8, 1);
    }
    // stage b[j] for this tile's columns
    float* bsh = reinterpret_cast<float*>(smem + TC_BSH);
    bsh[tid] = g_b[gn0 + tid];

    CP_WAIT(0);
    __syncthreads();

    uint32_t tmem_base;
    asm volatile("ld.shared.b32 %0, [%1];" : "=r"(tmem_base) : "r"(sb));

    if (wid == 0) {
        if (elect_one()) {
            FENCE_ASYNC();
            uint64_t ab = DESC_BASE | ((uint64_t)((sb + TC_A_OFF) >> 4) & 0x3FFF);
            uint64_t bb = DESC_BASE | ((uint64_t)((sb + TC_B_OFF) >> 4) & 0x3FFF);
            #pragma unroll
            for (int s = 0; s < 8; s++) {
                int kg = s >> 2, t = s & 3;
                MMA_F16_SS(tmem_base,
                           ab + (uint64_t)(kg * (TC_ASUB / 16) + t * 2),
                           bb + (uint64_t)(kg * (TC_BSUB / 16) + t * 2),
                           IDESC_TC, s ? 1u : 0u);
            }
            TC_COMMIT(sb + 8);
        }
    }

    mbar_wait(sb + 8, 0);
    TC_FENCE_AFTER();

    // epilogue: warp w covers rows (w&3)*32+lane, cols (w>>2)*128 .. +127
    const int   gi  = gm0 + (wid & 3) * 32 + lane;
    const float ai  = __ldg(&g_a[gi]);
    const int   cb0 = (wid >> 2) * 128;
    float s = 0.0f;
    #pragma unroll
    for (int c = 0; c < 4; c++) {
        uint32_t r[32];
        LDTM_X32(r, tmem_base + cb0 + c * 32);
        TC_WAIT_LD();
        #pragma unroll
        for (int j = 0; j < 32; j++) {
            int nj = cb0 + c * 32 + j;
            float v = fmaf(2.0f, __uint_as_float(r[j]), ai - bsh[nj]);
            if (gi != gn0 + nj && v > 0.0f) s += v;
        }
    }
    TC_FENCE_BEFORE();

    #pragma unroll
    for (int off = 16; off > 0; off >>= 1)
        s += __shfl_xor_sync(0xFFFFFFFFu, s, off);
    float* ws = reinterpret_cast<float*>(smem + TC_WS);
    if (lane == 0) ws[wid] = s;
    __syncthreads();
    if (tid == 0) {
        float t = 0.0f;
        #pragma unroll
        for (int w = 0; w < 8; w++) t += ws[w];
        g_tc[blockIdx.y * TC_NTN + blockIdx.x] = t;
    }
    if (wid == 0) {
        TC_RELINQ();
        TC_DEALLOC(tmem_base, 256);
    }
#endif
#endif
}

// ---------------------------------------------------------------------------
// Fallback: persistent mma.sync kernel (exact R12 structure, 61.6-62us).
// ---------------------------------------------------------------------------
__device__ __forceinline__ void load_chunk(uint32_t sb, int bid, int cj, int tid) {
    int t   = bid + (cj >> 1) * GRIDP;
    int gm0 = (t >> 6) * BM;
    int gn0 = (t & 63) * BN;
    int k0  = (cj & 1) * 64;
    uint32_t base = sb + (uint32_t)(cj % 3) * STB;
    #pragma unroll
    for (int i = 0; i < 4; i++) {
        int f = i * 256 + tid;
        int r = f >> 3, cc = f & 7;
        uint32_t off = (uint32_t)(r * 128 + ((cc ^ (r & 7)) << 4));
        cp16(base + off,        g_xs + (size_t)(gm0 + r) * KB + k0 + cc * 8);
        cp16(base + BOFF + off, g_ys + (size_t)(gn0 + r) * KB + k0 + cc * 8);
    }
}

__device__ __forceinline__ void compute_chunk(uint32_t base, int a_row, int a_kcl,
                                              int b_row, int b_kcl,
                                              float (&acc)[4][4][4]) {
    #pragma unroll
    for (int s = 0; s < 4; s++) {
        uint32_t af[4][4], bfr[2][4];
        #pragma unroll
        for (int mi = 0; mi < 4; mi++) {
            int m  = a_row + mi * 16;
            int kc = 2 * s + a_kcl;
            LDSM4(af[mi], base + (uint32_t)(m * 128 + ((kc ^ (m & 7)) << 4)));
        }
        #pragma unroll
        for (int nb = 0; nb < 2; nb++) {
            int n  = b_row + nb * 16;
            int kc = 2 * s + b_kcl;
            LDSM4(bfr[nb], base + BOFF + (uint32_t)(n * 128 + ((kc ^ (n & 7)) << 4)));
        }
        #pragma unroll
        for (int mi = 0; mi < 4; mi++) {
            #pragma unroll
            for (int nb = 0; nb < 2; nb++) {
                mma16816(acc[mi][2 * nb + 0], af[mi], bfr[nb][0], bfr[nb][1]);
                mma16816(acc[mi][2 * nb + 1], af[mi], bfr[nb][2], bfr[nb][3]);
            }
        }
    }
}

__global__ void __launch_bounds__(256, 2)
tile_kernel_fb() {
    extern __shared__ char smem[];
    const uint32_t sb = smem_u32(smem);
    const int bid  = blockIdx.x;
    const int tid  = threadIdx.x;
    const int wid  = tid >> 5;
    const int lane = tid & 31;
    const int wm   = wid >> 2;
    const int wn   = wid & 3;

    const int a_row = wm * 64 + ((lane >> 3) & 1) * 8 + (lane & 7);
    const int a_kcl = lane >> 4;
    const int b_row = wn * 32 + ((lane >> 4) & 1) * 8 + (lane & 7);
    const int b_kcl = (lane >> 3) & 1;
    const int g  = lane >> 2;
    const int tg = lane & 3;

    const int nt  = (NTILES - 1 - bid) / GRIDP + 1;
    const int nch = 2 * nt;

    load_chunk(sb, bid, 0, tid); CP_COMMIT();
    load_chunk(sb, bid, 1, tid); CP_COMMIT();

    float acc[4][4][4];
    #pragma unroll
    for (int i = 0; i < 4; i++)
        #pragma unroll
        for (int jj = 0; jj < 4; jj++)
            #pragma unroll
            for (int q = 0; q < 4; q++) acc[i][jj][q] = 0.0f;

    double s_run = 0.0;

    for (int j = 0; j < nch; j++) {
        CP_WAIT(1);
        __syncthreads();
        if (j + 2 < nch) load_chunk(sb, bid, j + 2, tid);
        CP_COMMIT();

        compute_chunk(sb + (uint32_t)(j % 3) * STB, a_row, a_kcl, b_row, b_kcl, acc);

        if (j & 1) {
            int t   = bid + (j >> 1) * GRIDP;
            int gm0 = (t >> 6) * BM;
            int gn0 = (t & 63) * BN;
            float s = 0.0f;
            #pragma unroll
            for (int mi = 0; mi < 4; mi++) {
                int gi0 = gm0 + wm * 64 + mi * 16 + g;
                int gi1 = gi0 + 8;
                float a0 = __ldg(&g_a[gi0]);
                float a1 = __ldg(&g_a[gi1]);
                #pragma unroll
                for (int ni = 0; ni < 4; ni++) {
                    int gj0 = gn0 + wn * 32 + ni * 8 + tg * 2;
                    int gj1 = gj0 + 1;
                    float2 bb = __ldg(reinterpret_cast<const float2*>(&g_b[gj0]));
                    float v;
                    v = fmaf(2.0f, acc[mi][ni][0], a0 - bb.x); if (gi0 != gj0 && v > 0.0f) s += v;
                    v = fmaf(2.0f, acc[mi][ni][1], a0 - bb.y); if (gi0 != gj1 && v > 0.0f) s += v;
                    v = fmaf(2.0f, acc[mi][ni][2], a1 - bb.x); if (gi1 != gj0 && v > 0.0f) s += v;
                    v = fmaf(2.0f, acc[mi][ni][3], a1 - bb.y); if (gi1 != gj1 && v > 0.0f) s += v;
                    acc[mi][ni][0] = 0.0f; acc[mi][ni][1] = 0.0f;
                    acc[mi][ni][2] = 0.0f; acc[mi][ni][3] = 0.0f;
                }
            }
            s_run += (double)s;
        }
    }

    #pragma unroll
    for (int off = 16; off > 0; off >>= 1)
        s_run += __shfl_xor_sync(0xFFFFFFFFu, s_run, off);
    double* wsum = reinterpret_cast<double*>(smem + WSUM_OFF);
    if (lane == 0) wsum[wid] = s_run;
    __syncthreads();
    if (tid == 0) {
        double tsum = 0.0;
        #pragma unroll
        for (int w = 0; w < 8; w++) tsum += wsum[w];
        g_cta[bid] = tsum;
    }
}

// ---------------------------------------------------------------------------
// Final reduction: sums BOTH partial arrays (inactive one is all-zero).
// ---------------------------------------------------------------------------
__global__ void reduce_kernel(float* __restrict__ out) {
    __shared__ double sh[8];
    int tid = threadIdx.x;   // 256 threads

    double s = 0.0;
    for (int t = tid; t < GRIDP; t += 256) s += g_cta[t];
    for (int t = tid; t < TC_NTM * TC_NTN; t += 256) s += (double)g_tc[t];

    #pragma unroll
    for (int off = 16; off > 0; off >>= 1)
        s += __shfl_xor_sync(0xFFFFFFFFu, s, off);
    if ((tid & 31) == 0) sh[tid >> 5] = s;
    __syncthreads();
    if (tid == 0) {
        double t = 0.0;
        #pragma unroll
        for (int w = 0; w < 8; w++) t += sh[w];
        out[0] = (float)(t / ((double)NROWS * (double)NROWS));
    }
}

// ---------------------------------------------------------------------------
extern "C" void kernel_launch(void* const* d_in, const int* in_sizes, int n_in,
                              void* d_out, int out_size) {
    const float* x = (const float*)d_in[0];
    const float* y = (const float*)d_in[1];
    float* out = (float*)d_out;

    // Detect whether the tcgen05 body was compiled for the loaded arch:
    // the feature-guarded kernel is empty (few regs) on non-103a passes.
    cudaFuncAttributes at{};
    cudaFuncGetAttributes(&at, tile_kernel_tc);
    const bool use_tc = at.numRegs > 32;

    precompute_kernel<<<NROWS / 8, 256>>>(x, y);

    if (use_tc) {
        cudaFuncSetAttribute(tile_kernel_tc,
                             cudaFuncAttributeMaxDynamicSharedMemorySize, SMEM_TC);
        tile_kernel_tc<<<dim3(TC_NTN, TC_NTM), 256, SMEM_TC>>>();
    } else {
        cudaFuncSetAttribute(tile_kernel_fb,
                             cudaFuncAttributeMaxDynamicSharedMemorySize, SMEM_FB);
        tile_kernel_fb<<<GRIDP, 256, SMEM_FB>>>();
    }

    reduce_kernel<<<1, 256>>>(out);
}